// round 11
// baseline (speedup 1.0000x reference)
#include <cuda_runtime.h>
#include <cstddef>

#define B 8
#define L 2048
#define H 8
#define D 64
#define BH 64
#define SK 40
#define U  40
#define HD 512
#define SCALE 0.125f
#define NT 8            // probe key tiles of 256 rows
#define QC2 256         // probe queries per block
#define KS 16           // attention key splits
#define AKT 128         // attention key tile
#define FILLB 32        // fill slabs per bh (64 rows each)

// ---- device scratch ----
__device__ float g_M[BH * L];
__device__ int   g_top[BH * U];
__device__ float g_vmean[BH * D];
__device__ unsigned char g_ent[L * SK];
__device__ unsigned char g_off[L * (NT + 1)];
__device__ float g_pv[(size_t)BH * KS * U * D];      // 10.5 MB combined PV
__device__ float g_ml[BH * KS * U * 2];              // (m, l) per split

// ------------------------------------------------------------------
// Build per-q inverted sample lists bucketed by 256-row key tile,
// stable in s within each tile (deterministic accumulation order).
// ------------------------------------------------------------------
__global__ void k_build(const int* __restrict__ IS) {
    int q = blockIdx.x * blockDim.x + threadIdx.x;
    if (q >= L) return;
    int idxs[SK];
    int cnt[NT];
    #pragma unroll
    for (int t = 0; t < NT; ++t) cnt[t] = 0;
    #pragma unroll
    for (int s = 0; s < SK; ++s) {
        idxs[s] = IS[q * SK + s];
        cnt[idxs[s] >> 8]++;
    }
    int off[NT + 1];
    off[0] = 0;
    #pragma unroll
    for (int t = 0; t < NT; ++t) off[t + 1] = off[t] + cnt[t];
    #pragma unroll
    for (int t = 0; t <= NT; ++t) g_off[q * (NT + 1) + t] = (unsigned char)off[t];
    int pos[NT];
    #pragma unroll
    for (int t = 0; t < NT; ++t) pos[t] = off[t];
    #pragma unroll
    for (int s = 0; s < SK; ++s) {
        int t = idxs[s] >> 8;
        g_ent[q * SK + pos[t]++] = (unsigned char)(idxs[s] & 255);
    }
}

// ------------------------------------------------------------------
// Probe v9: thread-per-query smem gather, PROVABLY conflict-free.
// K tile pitch 16 float4 (quad = chunk&7); lane l reads chunks in
// rotated order (c+l)&15 -> every 8-lane phase hits quads {0..7}
// exactly once regardless of random row indices. Q registers are
// pre-rotated so all register indices are static. No cross-lane ops.
// ------------------------------------------------------------------
__global__ __launch_bounds__(256, 2) void k_probe9(const float* __restrict__ Q,
                                                   const float* __restrict__ Kp) {
    extern __shared__ float ksm[];                   // 256 * 64 floats = 64 KB
    __shared__ unsigned char ent_sm[QC2 * SK];       // 10240 B
    __shared__ unsigned char off_sm[QC2 * (NT + 1)]; // 2304 B
    float4* ksm4 = (float4*)ksm;                     // row pitch 16 float4

    int bh = blockIdx.y, qc = blockIdx.x;
    int b = bh >> 3, h = bh & 7;
    int t = threadIdx.x;
    int rot = t & 15;                                // lane&15 rotation
    int qbase0 = qc * QC2;

    {   // stage entry lists + offsets
        const uint4* esrc = (const uint4*)(g_ent + (size_t)qbase0 * SK);
        uint4* edst = (uint4*)ent_sm;
        for (int i = t; i < QC2 * SK / 16; i += 256) edst[i] = esrc[i];
        const unsigned* osrc = (const unsigned*)(g_off + (size_t)qbase0 * (NT + 1));
        unsigned* odst = (unsigned*)off_sm;
        for (int i = t; i < QC2 * (NT + 1) / 4; i += 256) odst[i] = osrc[i];
    }

    // Q row, pre-rotated: qv[c] = chunk (c+rot)&15 of this query's row
    float4 qv[16];
    {
        const float4* qrow = (const float4*)(Q + (size_t)(b * L + qbase0 + t) * HD + h * D);
        #pragma unroll
        for (int c = 0; c < 16; ++c) qv[c] = qrow[(c + rot) & 15];
    }

    float mx = -3.4e38f, sm = 0.f;
    const float4* Ksrc0 = (const float4*)(Kp + (size_t)(b * L) * HD + h * D);

    for (int kt = 0; kt < NT; ++kt) {
        __syncthreads();
        const float4* src = Ksrc0 + (size_t)(kt * 256) * (HD / 4);
        for (int i = t; i < 256 * 16; i += 256) {
            int r = i >> 4, c = i & 15;
            ksm4[r * 16 + c] = src[(size_t)r * (HD / 4) + c];
        }
        __syncthreads();

        int o0 = off_sm[t * (NT + 1) + kt];
        int o1 = off_sm[t * (NT + 1) + kt + 1];
        const unsigned char* ep = ent_sm + t * SK;
        for (int e = o0; e < o1; ++e) {
            int kl = ep[e];
            const float4* kr = ksm4 + kl * 16;
            float a0 = 0.f, a1 = 0.f, a2 = 0.f, a3 = 0.f;
            #pragma unroll
            for (int c = 0; c < 16; c += 4) {
                float4 k0 = kr[(c + rot) & 15];
                float4 k1 = kr[(c + 1 + rot) & 15];
                float4 k2 = kr[(c + 2 + rot) & 15];
                float4 k3 = kr[(c + 3 + rot) & 15];
                a0 = fmaf(qv[c].x,     k0.x, a0); a0 = fmaf(qv[c].y,     k0.y, a0);
                a0 = fmaf(qv[c].z,     k0.z, a0); a0 = fmaf(qv[c].w,     k0.w, a0);
                a1 = fmaf(qv[c + 1].x, k1.x, a1); a1 = fmaf(qv[c + 1].y, k1.y, a1);
                a1 = fmaf(qv[c + 1].z, k1.z, a1); a1 = fmaf(qv[c + 1].w, k1.w, a1);
                a2 = fmaf(qv[c + 2].x, k2.x, a2); a2 = fmaf(qv[c + 2].y, k2.y, a2);
                a2 = fmaf(qv[c + 2].z, k2.z, a2); a2 = fmaf(qv[c + 2].w, k2.w, a2);
                a3 = fmaf(qv[c + 3].x, k3.x, a3); a3 = fmaf(qv[c + 3].y, k3.y, a3);
                a3 = fmaf(qv[c + 3].z, k3.z, a3); a3 = fmaf(qv[c + 3].w, k3.w, a3);
            }
            float p = (a0 + a1) + (a2 + a3);
            mx = fmaxf(mx, p);
            sm += p;
        }
    }
    g_M[bh * L + qbase0 + t] = mx - sm * (1.f / SK);
}

// ------------------------------------------------------------------
// phase2: blocks 0-63 = top-40 per bh; blocks 64-127 = V mean per bh.
// ------------------------------------------------------------------
__global__ __launch_bounds__(512) void k_phase2(const float* __restrict__ V) {
    __shared__ unsigned long long cand[16 * U];   // topk
    __shared__ float vsm[8 * 64];                 // vmean
    int bh = blockIdx.x & 63;
    int role = blockIdx.x >> 6;
    int t = threadIdx.x;

    if (role == 1) {      // ---- vmean ----
        int b = bh >> 3, h = bh & 7;
        int d = t & 63, p = t >> 6;   // p 0..7
        float s = 0.f;
        for (int l = p; l < L; l += 8)
            s += V[(size_t)(b * L + l) * HD + h * D + d];
        vsm[p * 64 + d] = s;
        __syncthreads();
        if (t < 64) {
            float acc = 0.f;
            #pragma unroll
            for (int i = 0; i < 8; ++i) acc += vsm[i * 64 + t];
            g_vmean[bh * 64 + t] = acc * (1.f / L);
        }
        return;
    }

    // ---- topk ----
    int w = t >> 5, lane = t & 31;
    unsigned long long k[4];
    #pragma unroll
    for (int j = 0; j < 4; ++j) {
        int i = w * 128 + j * 32 + lane;
        unsigned bits = __float_as_uint(g_M[bh * L + i]);
        bits = (bits & 0x80000000u) ? ~bits : (bits | 0x80000000u);
        k[j] = ((unsigned long long)bits << 32) | (unsigned)(L - 1 - i);
    }
    for (int it = 0; it < U; ++it) {
        unsigned long long lm = k[0];
        #pragma unroll
        for (int j = 1; j < 4; ++j) if (k[j] > lm) lm = k[j];
        unsigned long long wm = lm;
        #pragma unroll
        for (int o = 16; o; o >>= 1) {
            unsigned long long x = __shfl_xor_sync(0xffffffffu, wm, o);
            if (x > wm) wm = x;
        }
        if (lane == 0) cand[w * U + it] = wm;
        #pragma unroll
        for (int j = 0; j < 4; ++j) if (k[j] == wm) k[j] = 0ull;
    }
    __syncthreads();
    for (int i = t; i < 16 * U; i += 512) {
        unsigned long long me = cand[i];
        int rank = 0;
        #pragma unroll 4
        for (int j = 0; j < 16 * U; j += 2) {
            rank += (cand[j]     > me) ? 1 : 0;
            rank += (cand[j + 1] > me) ? 1 : 0;
        }
        if (rank < U)
            g_top[bh * U + rank] = (L - 1) - (int)(me & 0xffffffffu);
    }
}

// ------------------------------------------------------------------
// phase3: blockIdx.x < KS -> fused scores+softmax+PV split (kh halves
// combined in smem before the single g_pv write); else -> fill slab.
// ------------------------------------------------------------------
__global__ __launch_bounds__(256, 3) void k_phase3(const float* __restrict__ Q,
                                                   const float* __restrict__ Kp,
                                                   const float* __restrict__ V,
                                                   float* __restrict__ out) {
    extern __shared__ float smem[];
    int bh = blockIdx.y;
    int b = bh >> 3, h = bh & 7;
    int t = threadIdx.x;

    if (blockIdx.x >= KS) {    // ---- fill slab ----
        int j = blockIdx.x - KS;          // 0..31
        int l0 = j * 64;
        const float4* vm4 = (const float4*)&g_vmean[bh * 64];
        float4* out4 = (float4*)out;
        #pragma unroll
        for (int kk = 0; kk < 4; ++kk) {
            int fi  = t + kk * 256;       // 0..1023
            int row = fi >> 4, c4 = fi & 15;
            out4[(size_t)(b * L + l0 + row) * (HD / 4) + h * 16 + c4] = vm4[c4];
        }
        return;
    }

    // ---- attn split ----
    float* Qsm  = smem;            // 40*64  = 2560 (reused as PV combine buf)
    float* KVsm = smem + 2560;     // 128*68 = 8704
    float* Asm  = KVsm + 8704;     // 40*132 = 5280
    int ks = blockIdx.x;
    int k0 = ks * AKT;

    for (int i = t; i < U * 16; i += 256) {
        int u = i >> 4, dq = i & 15;
        int qi = g_top[bh * U + u];
        *(float4*)&Qsm[u * 64 + dq * 4] =
            *(const float4*)&Q[(size_t)(b * L + qi) * HD + h * D + dq * 4];
    }
    for (int i = t; i < AKT * 16; i += 256) {
        int r = i >> 4, dq = i & 15;
        *(float4*)&KVsm[r * 68 + dq * 4] =
            *(const float4*)&Kp[(size_t)(b * L + k0 + r) * HD + h * D + dq * 4];
    }
    __syncthreads();

    {   // scores: thread = (kg 0..63, ug 0..3)
        int kg = t & 63, ug = t >> 6;
        float acc[10][2];
        #pragma unroll
        for (int i = 0; i < 10; ++i) { acc[i][0] = 0.f; acc[i][1] = 0.f; }
        for (int d = 0; d < 64; d += 4) {
            float4 ka = *(float4*)&KVsm[kg * 68 + d];
            float4 kb = *(float4*)&KVsm[(kg + 64) * 68 + d];
            #pragma unroll
            for (int i = 0; i < 10; ++i) {
                float4 q4 = *(float4*)&Qsm[(ug * 10 + i) * 64 + d];
                acc[i][0] = fmaf(q4.x, ka.x, acc[i][0]);
                acc[i][0] = fmaf(q4.y, ka.y, acc[i][0]);
                acc[i][0] = fmaf(q4.z, ka.z, acc[i][0]);
                acc[i][0] = fmaf(q4.w, ka.w, acc[i][0]);
                acc[i][1] = fmaf(q4.x, kb.x, acc[i][1]);
                acc[i][1] = fmaf(q4.y, kb.y, acc[i][1]);
                acc[i][1] = fmaf(q4.z, kb.z, acc[i][1]);
                acc[i][1] = fmaf(q4.w, kb.w, acc[i][1]);
            }
        }
        #pragma unroll
        for (int i = 0; i < 10; ++i) {
            Asm[(ug * 10 + i) * 132 + kg]      = acc[i][0] * SCALE;
            Asm[(ug * 10 + i) * 132 + kg + 64] = acc[i][1] * SCALE;
        }
    }
    __syncthreads();

    // V -> KVsm; per-row (m, l) stats
    for (int i = t; i < AKT * 16; i += 256) {
        int r = i >> 4, dq = i & 15;
        *(float4*)&KVsm[r * 68 + dq * 4] =
            *(const float4*)&V[(size_t)(b * L + k0 + r) * HD + h * D + dq * 4];
    }
    {
        int w = t >> 5, lane = t & 31;
        #pragma unroll
        for (int rr = 0; rr < 5; ++rr) {
            int u = w * 5 + rr;
            float vals[4], m = -3.4e38f;
            #pragma unroll
            for (int mm = 0; mm < 4; ++mm) {
                vals[mm] = Asm[u * 132 + lane + 32 * mm];
                m = fmaxf(m, vals[mm]);
            }
            #pragma unroll
            for (int o = 16; o; o >>= 1) m = fmaxf(m, __shfl_xor_sync(0xffffffffu, m, o));
            float lsum = 0.f;
            #pragma unroll
            for (int mm = 0; mm < 4; ++mm) {
                float pe = __expf(vals[mm] - m);
                Asm[u * 132 + lane + 32 * mm] = pe;
                lsum += pe;
            }
            #pragma unroll
            for (int o = 16; o; o >>= 1) lsum += __shfl_xor_sync(0xffffffffu, lsum, o);
            if (lane == 0) {
                g_ml[((bh * KS + ks) * U + u) * 2 + 0] = m;
                g_ml[((bh * KS + ks) * U + u) * 2 + 1] = lsum;
            }
        }
    }
    __syncthreads();

    {   // PV: thread = (kh 0..1, ug2 0..7, dg 0..15); kh halves combined in smem
        int kh = t >> 7, ug2 = (t >> 4) & 7, dg = t & 15;
        int kb = kh * 64;
        float4 o[5];
        #pragma unroll
        for (int i = 0; i < 5; ++i) o[i] = make_float4(0.f, 0.f, 0.f, 0.f);
        for (int k = 0; k < 64; ++k) {
            float4 v = *(float4*)&KVsm[(kb + k) * 68 + dg * 4];
            #pragma unroll
            for (int i = 0; i < 5; ++i) {
                float a = Asm[(ug2 * 5 + i) * 132 + kb + k];
                o[i].x = fmaf(a, v.x, o[i].x);
                o[i].y = fmaf(a, v.y, o[i].y);
                o[i].z = fmaf(a, v.z, o[i].z);
                o[i].w = fmaf(a, v.w, o[i].w);
            }
        }
        if (kh == 1) {   // park upper-half partials in Qsm (40*64 floats)
            #pragma unroll
            for (int i = 0; i < 5; ++i)
                *(float4*)&Qsm[(ug2 * 5 + i) * 64 + dg * 4] = o[i];
        }
        __syncthreads();
        if (kh == 0) {
            #pragma unroll
            for (int i = 0; i < 5; ++i) {
                float4 p1 = *(float4*)&Qsm[(ug2 * 5 + i) * 64 + dg * 4];
                o[i].x += p1.x; o[i].y += p1.y; o[i].z += p1.z; o[i].w += p1.w;
                *(float4*)&g_pv[(size_t)((bh * KS + ks) * U + ug2 * 5 + i) * D + dg * 4] = o[i];
            }
        }
    }
}

// ------------------------------------------------------------------
// Combine split-K partials with softmax rescale, scatter to output
// ------------------------------------------------------------------
__global__ void k_final(float* __restrict__ out) {
    int i4 = blockIdx.x * blockDim.x + threadIdx.x;
    if (i4 >= BH * U * 16) return;
    int dq = i4 & 15;
    int u  = (i4 >> 4) % U;
    int bh = i4 / (U * 16);

    float mv[KS], lv[KS], M = -3.4e38f;
    #pragma unroll
    for (int s = 0; s < KS; ++s) {
        mv[s] = g_ml[((bh * KS + s) * U + u) * 2 + 0];
        lv[s] = g_ml[((bh * KS + s) * U + u) * 2 + 1];
        M = fmaxf(M, mv[s]);
    }
    float4 acc = make_float4(0.f, 0.f, 0.f, 0.f);
    float lsum = 0.f;
    #pragma unroll
    for (int s = 0; s < KS; ++s) {
        float wgt = __expf(mv[s] - M);
        lsum += wgt * lv[s];
        float4 p = *(const float4*)&g_pv[(size_t)((bh * KS + s) * U + u) * D + dq * 4];
        acc.x = fmaf(wgt, p.x, acc.x);
        acc.y = fmaf(wgt, p.y, acc.y);
        acc.z = fmaf(wgt, p.z, acc.z);
        acc.w = fmaf(wgt, p.w, acc.w);
    }
    float inv = 1.f / lsum;
    int q = g_top[bh * U + u];
    int b = bh >> 3, h = bh & 7;
    *(float4*)&out[(size_t)(b * L + q) * HD + h * D + dq * 4] =
        make_float4(acc.x * inv, acc.y * inv, acc.z * inv, acc.w * inv);
}

// ------------------------------------------------------------------
extern "C" void kernel_launch(void* const* d_in, const int* in_sizes, int n_in,
                              void* d_out, int out_size) {
    const float* Q = (const float*)d_in[0];
    const float* K = (const float*)d_in[1];
    const float* V = (const float*)d_in[2];
    const int*  IS = (const int*)d_in[3];
    float* out = (float*)d_out;

    const int smem_probe = 256 * 64 * 4;              // 65536 dynamic
    const int smem_attn  = (2560 + 8704 + 5280) * 4;  // 66176
    cudaFuncSetAttribute(k_probe9, cudaFuncAttributeMaxDynamicSharedMemorySize, smem_probe);
    cudaFuncSetAttribute(k_phase3, cudaFuncAttributeMaxDynamicSharedMemorySize, smem_attn);

    k_build  <<<(L + 255) / 256, 256>>>(IS);
    k_probe9 <<<dim3(L / QC2, BH), 256, smem_probe>>>(Q, K);
    k_phase2 <<<128, 512>>>(V);                                        // topk || vmean
    k_phase3 <<<dim3(KS + FILLB, BH), 256, smem_attn>>>(Q, K, V, out); // attn || fill
    k_final  <<<(BH * U * 16 + 255) / 256, 256>>>(out);
}

// round 12
// speedup vs baseline: 1.1921x; 1.1921x over previous
#include <cuda_runtime.h>
#include <cstddef>

#define B 8
#define L 2048
#define H 8
#define D 64
#define BH 64
#define SK 40
#define U  40
#define HD 512
#define SCALE 0.125f
#define KS 16           // attention key splits
#define AKT 128         // attention key tile
#define FILLB 32        // fill slabs per bh (64 rows each)
#define PROBE_BLKS 8192 // probe role blocks

// ---- device scratch ----
__device__ float g_M[BH * L];
__device__ int   g_top[BH * U];
__device__ float g_vmean[BH * D];
__device__ float g_pv[(size_t)BH * KS * 2 * U * D];  // partial PV (two kh halves)
__device__ float g_ml[BH * KS * U * 2];              // (m, l) per split

// ------------------------------------------------------------------
// phase1: blocks < PROBE_BLKS -> probe (L2-roofline bound ~124us):
// M = max_s - mean_s; 2 queries/warp, 16 lanes/query, 4-step reduce.
// blocks >= PROBE_BLKS -> V mean per bh (hidden in probe's shadow).
// ------------------------------------------------------------------
__global__ void k_phase1(const float* __restrict__ Q, const float* __restrict__ Kp,
                         const float* __restrict__ V, const int* __restrict__ IS) {
    __shared__ float vsm[4 * 64];
    if (blockIdx.x >= PROBE_BLKS) {      // ---- vmean role ----
        int bh = blockIdx.x - PROBE_BLKS;
        int b = bh >> 3, h = bh & 7;
        int d = threadIdx.x & 63, p = threadIdx.x >> 6;
        float s = 0.f;
        for (int l = p; l < L; l += 4)
            s += V[(size_t)(b * L + l) * HD + h * D + d];
        vsm[p * 64 + d] = s;
        __syncthreads();
        if (threadIdx.x < 64) {
            float t = vsm[threadIdx.x] + vsm[64 + threadIdx.x]
                    + vsm[128 + threadIdx.x] + vsm[192 + threadIdx.x];
            g_vmean[bh * 64 + threadIdx.x] = t * (1.f / L);
        }
        return;
    }

    // ---- probe role ----
    int wg   = blockIdx.x * (blockDim.x >> 5) + (threadIdx.x >> 5);
    int lane = threadIdx.x & 31;
    int qh   = lane >> 4;
    int li   = lane & 15;
    int qi   = wg * 2 + qh;
    int bh   = qi >> 11;
    int q    = qi & (L - 1);
    int b = bh >> 3, h = bh & 7;

    float4 ql = *(const float4*)(Q + (size_t)(b * L + q) * HD + h * D + 4 * li);
    const int* isrow = IS + q * SK;
    float mx = -3.4e38f, sm = 0.f;
    #pragma unroll 4
    for (int s = 0; s < SK; ++s) {
        int idx = __ldg(isrow + s);
        float4 kv = *(const float4*)(Kp + (size_t)(b * L + idx) * HD + h * D + 4 * li);
        float p = ql.x * kv.x + ql.y * kv.y + ql.z * kv.z + ql.w * kv.w;
        p += __shfl_xor_sync(0xffffffffu, p, 8);
        p += __shfl_xor_sync(0xffffffffu, p, 4);
        p += __shfl_xor_sync(0xffffffffu, p, 2);
        p += __shfl_xor_sync(0xffffffffu, p, 1);
        mx = fmaxf(mx, p);
        sm += p;
    }
    if (li == 0) g_M[bh * L + q] = mx - sm * (1.f / SK);
}

// ------------------------------------------------------------------
// phase2: top-40 per bh. 16 warps x 128-elem slices (4 keys/lane) ->
// rank-select over 640 unique candidates (g_top order irrelevant).
// ------------------------------------------------------------------
__global__ __launch_bounds__(512) void k_phase2() {
    __shared__ unsigned long long cand[16 * U];
    int bh = blockIdx.x;
    int t = threadIdx.x, w = t >> 5, lane = t & 31;

    unsigned long long k[4];
    #pragma unroll
    for (int j = 0; j < 4; ++j) {
        int i = w * 128 + j * 32 + lane;
        unsigned bits = __float_as_uint(g_M[bh * L + i]);
        bits = (bits & 0x80000000u) ? ~bits : (bits | 0x80000000u);
        k[j] = ((unsigned long long)bits << 32) | (unsigned)(L - 1 - i);
    }
    for (int it = 0; it < U; ++it) {
        unsigned long long lm = k[0];
        #pragma unroll
        for (int j = 1; j < 4; ++j) if (k[j] > lm) lm = k[j];
        unsigned long long wm = lm;
        #pragma unroll
        for (int o = 16; o; o >>= 1) {
            unsigned long long x = __shfl_xor_sync(0xffffffffu, wm, o);
            if (x > wm) wm = x;
        }
        if (lane == 0) cand[w * U + it] = wm;
        #pragma unroll
        for (int j = 0; j < 4; ++j) if (k[j] == wm) k[j] = 0ull;
    }
    __syncthreads();
    for (int i = t; i < 16 * U; i += 512) {
        unsigned long long me = cand[i];
        int rank = 0;
        #pragma unroll 4
        for (int j = 0; j < 16 * U; j += 2) {
            rank += (cand[j]     > me) ? 1 : 0;
            rank += (cand[j + 1] > me) ? 1 : 0;
        }
        if (rank < U)
            g_top[bh * U + rank] = (L - 1) - (int)(me & 0xffffffffu);
    }
}

// ------------------------------------------------------------------
// phase3 (r10-measured form): blockIdx.x < KS -> fused
// scores+softmax+PV split; else -> fill slab (hidden under attn).
// ------------------------------------------------------------------
__global__ __launch_bounds__(256, 3) void k_phase3(const float* __restrict__ Q,
                                                   const float* __restrict__ Kp,
                                                   const float* __restrict__ V,
                                                   float* __restrict__ out) {
    extern __shared__ float smem[];
    int bh = blockIdx.y;
    int b = bh >> 3, h = bh & 7;
    int t = threadIdx.x;

    if (blockIdx.x >= KS) {    // ---- fill slab ----
        int j = blockIdx.x - KS;          // 0..31
        int l0 = j * 64;
        const float4* vm4 = (const float4*)&g_vmean[bh * 64];
        float4* out4 = (float4*)out;
        #pragma unroll
        for (int kk = 0; kk < 4; ++kk) {
            int fi  = t + kk * 256;       // 0..1023
            int row = fi >> 4, c4 = fi & 15;
            out4[(size_t)(b * L + l0 + row) * (HD / 4) + h * 16 + c4] = vm4[c4];
        }
        return;
    }

    // ---- attn split ----
    float* Qsm  = smem;            // 40*64  = 2560
    float* KVsm = smem + 2560;     // 128*68 = 8704
    float* Asm  = KVsm + 8704;     // 40*132 = 5280
    int ks = blockIdx.x;
    int k0 = ks * AKT;

    for (int i = t; i < U * 16; i += 256) {
        int u = i >> 4, dq = i & 15;
        int qi = g_top[bh * U + u];
        *(float4*)&Qsm[u * 64 + dq * 4] =
            *(const float4*)&Q[(size_t)(b * L + qi) * HD + h * D + dq * 4];
    }
    for (int i = t; i < AKT * 16; i += 256) {
        int r = i >> 4, dq = i & 15;
        *(float4*)&KVsm[r * 68 + dq * 4] =
            *(const float4*)&Kp[(size_t)(b * L + k0 + r) * HD + h * D + dq * 4];
    }
    __syncthreads();

    {   // scores: thread = (kg 0..63, ug 0..3)
        int kg = t & 63, ug = t >> 6;
        float acc[10][2];
        #pragma unroll
        for (int i = 0; i < 10; ++i) { acc[i][0] = 0.f; acc[i][1] = 0.f; }
        for (int d = 0; d < 64; d += 4) {
            float4 ka = *(float4*)&KVsm[kg * 68 + d];
            float4 kb = *(float4*)&KVsm[(kg + 64) * 68 + d];
            #pragma unroll
            for (int i = 0; i < 10; ++i) {
                float4 q4 = *(float4*)&Qsm[(ug * 10 + i) * 64 + d];
                acc[i][0] = fmaf(q4.x, ka.x, acc[i][0]);
                acc[i][0] = fmaf(q4.y, ka.y, acc[i][0]);
                acc[i][0] = fmaf(q4.z, ka.z, acc[i][0]);
                acc[i][0] = fmaf(q4.w, ka.w, acc[i][0]);
                acc[i][1] = fmaf(q4.x, kb.x, acc[i][1]);
                acc[i][1] = fmaf(q4.y, kb.y, acc[i][1]);
                acc[i][1] = fmaf(q4.z, kb.z, acc[i][1]);
                acc[i][1] = fmaf(q4.w, kb.w, acc[i][1]);
            }
        }
        #pragma unroll
        for (int i = 0; i < 10; ++i) {
            Asm[(ug * 10 + i) * 132 + kg]      = acc[i][0] * SCALE;
            Asm[(ug * 10 + i) * 132 + kg + 64] = acc[i][1] * SCALE;
        }
    }
    __syncthreads();

    // V -> KVsm; per-row (m, l) stats
    for (int i = t; i < AKT * 16; i += 256) {
        int r = i >> 4, dq = i & 15;
        *(float4*)&KVsm[r * 68 + dq * 4] =
            *(const float4*)&V[(size_t)(b * L + k0 + r) * HD + h * D + dq * 4];
    }
    {
        int w = t >> 5, lane = t & 31;
        #pragma unroll
        for (int rr = 0; rr < 5; ++rr) {
            int u = w * 5 + rr;
            float vals[4], m = -3.4e38f;
            #pragma unroll
            for (int mm = 0; mm < 4; ++mm) {
                vals[mm] = Asm[u * 132 + lane + 32 * mm];
                m = fmaxf(m, vals[mm]);
            }
            #pragma unroll
            for (int o = 16; o; o >>= 1) m = fmaxf(m, __shfl_xor_sync(0xffffffffu, m, o));
            float lsum = 0.f;
            #pragma unroll
            for (int mm = 0; mm < 4; ++mm) {
                float pe = __expf(vals[mm] - m);
                Asm[u * 132 + lane + 32 * mm] = pe;
                lsum += pe;
            }
            #pragma unroll
            for (int o = 16; o; o >>= 1) lsum += __shfl_xor_sync(0xffffffffu, lsum, o);
            if (lane == 0) {
                g_ml[((bh * KS + ks) * U + u) * 2 + 0] = m;
                g_ml[((bh * KS + ks) * U + u) * 2 + 1] = lsum;
            }
        }
    }
    __syncthreads();

    {   // PV: thread = (kh 0..1, ug2 0..7, dg 0..15)
        int kh = t >> 7, ug2 = (t >> 4) & 7, dg = t & 15;
        int kb = kh * 64;
        float4 o[5];
        #pragma unroll
        for (int i = 0; i < 5; ++i) o[i] = make_float4(0.f, 0.f, 0.f, 0.f);
        for (int k = 0; k < 64; ++k) {
            float4 v = *(float4*)&KVsm[(kb + k) * 68 + dg * 4];
            #pragma unroll
            for (int i = 0; i < 5; ++i) {
                float a = Asm[(ug2 * 5 + i) * 132 + kb + k];
                o[i].x = fmaf(a, v.x, o[i].x);
                o[i].y = fmaf(a, v.y, o[i].y);
                o[i].z = fmaf(a, v.z, o[i].z);
                o[i].w = fmaf(a, v.w, o[i].w);
            }
        }
        #pragma unroll
        for (int i = 0; i < 5; ++i)
            *(float4*)&g_pv[(size_t)(((bh * KS + ks) * 2 + kh) * U + ug2 * 5 + i) * D + dg * 4] = o[i];
    }
}

// ------------------------------------------------------------------
// Combine split-K partials with softmax rescale, scatter to output
// ------------------------------------------------------------------
__global__ void k_final(float* __restrict__ out) {
    int i4 = blockIdx.x * blockDim.x + threadIdx.x;
    if (i4 >= BH * U * 16) return;
    int dq = i4 & 15;
    int u  = (i4 >> 4) % U;
    int bh = i4 / (U * 16);

    float mv[KS], lv[KS], M = -3.4e38f;
    #pragma unroll
    for (int s = 0; s < KS; ++s) {
        mv[s] = g_ml[((bh * KS + s) * U + u) * 2 + 0];
        lv[s] = g_ml[((bh * KS + s) * U + u) * 2 + 1];
        M = fmaxf(M, mv[s]);
    }
    float4 acc = make_float4(0.f, 0.f, 0.f, 0.f);
    float lsum = 0.f;
    #pragma unroll
    for (int s = 0; s < KS; ++s) {
        float wgt = __expf(mv[s] - M);
        lsum += wgt * lv[s];
        float4 p0 = *(const float4*)&g_pv[(size_t)(((bh * KS + s) * 2 + 0) * U + u) * D + dq * 4];
        float4 p1 = *(const float4*)&g_pv[(size_t)(((bh * KS + s) * 2 + 1) * U + u) * D + dq * 4];
        acc.x = fmaf(wgt, p0.x + p1.x, acc.x);
        acc.y = fmaf(wgt, p0.y + p1.y, acc.y);
        acc.z = fmaf(wgt, p0.z + p1.z, acc.z);
        acc.w = fmaf(wgt, p0.w + p1.w, acc.w);
    }
    float inv = 1.f / lsum;
    int q = g_top[bh * U + u];
    int b = bh >> 3, h = bh & 7;
    *(float4*)&out[(size_t)(b * L + q) * HD + h * D + dq * 4] =
        make_float4(acc.x * inv, acc.y * inv, acc.z * inv, acc.w * inv);
}

// ------------------------------------------------------------------
extern "C" void kernel_launch(void* const* d_in, const int* in_sizes, int n_in,
                              void* d_out, int out_size) {
    const float* Q = (const float*)d_in[0];
    const float* K = (const float*)d_in[1];
    const float* V = (const float*)d_in[2];
    const int*  IS = (const int*)d_in[3];
    float* out = (float*)d_out;

    const int smem_attn = (2560 + 8704 + 5280) * 4;   // 66176
    cudaFuncSetAttribute(k_phase3, cudaFuncAttributeMaxDynamicSharedMemorySize, smem_attn);

    k_phase1<<<PROBE_BLKS + BH, 256>>>(Q, K, V, IS);                // probe || vmean
    k_phase2<<<BH, 512>>>();                                        // topk
    k_phase3<<<dim3(KS + FILLB, BH), 256, smem_attn>>>(Q, K, V, out); // attn || fill
    k_final <<<(BH * U * 16 + 255) / 256, 256>>>(out);
}

// round 17
// speedup vs baseline: 1.2649x; 1.0611x over previous
#include <cuda_runtime.h>
#include <cstddef>

#define B 8
#define L 2048
#define H 8
#define D 64
#define BH 64
#define SK 40
#define U  40
#define HD 512
#define SCALE 0.125f
#define KS 16           // attention key splits
#define AKT 128         // attention key tile
#define FILLB 32        // fill slabs per bh (64 rows each)

// ---- device scratch ----
__device__ float g_M[BH * L];
__device__ int   g_top[BH * U];
__device__ float g_vmean[BH * D];
__device__ float g_pv[(size_t)BH * KS * 2 * U * D];  // partial PV
__device__ float g_ml[BH * KS * U * 2];              // (m, l) per split

// ------------------------------------------------------------------
// Probe (L2-roofline bound ~124us): M = max_s - mean_s.
// 2 queries per warp; 16 lanes per query; 4-step half-warp reduce.
// ------------------------------------------------------------------
__global__ void k_probe_M(const float* __restrict__ Q, const float* __restrict__ Kp,
                          const int* __restrict__ IS) {
    int wg   = blockIdx.x * (blockDim.x >> 5) + (threadIdx.x >> 5);
    int lane = threadIdx.x & 31;
    int qh   = lane >> 4;
    int li   = lane & 15;
    int qi   = wg * 2 + qh;
    int bh   = qi >> 11;
    int q    = qi & (L - 1);
    int b = bh >> 3, h = bh & 7;

    float4 ql = *(const float4*)(Q + (size_t)(b * L + q) * HD + h * D + 4 * li);
    const int* isrow = IS + q * SK;
    float mx = -3.4e38f, sm = 0.f;
    #pragma unroll 4
    for (int s = 0; s < SK; ++s) {
        int idx = __ldg(isrow + s);
        float4 kv = *(const float4*)(Kp + (size_t)(b * L + idx) * HD + h * D + 4 * li);
        float p = ql.x * kv.x + ql.y * kv.y + ql.z * kv.z + ql.w * kv.w;
        p += __shfl_xor_sync(0xffffffffu, p, 8);
        p += __shfl_xor_sync(0xffffffffu, p, 4);
        p += __shfl_xor_sync(0xffffffffu, p, 2);
        p += __shfl_xor_sync(0xffffffffu, p, 1);
        mx = fmaxf(mx, p);
        sm += p;
    }
    if (li == 0) g_M[bh * L + q] = mx - sm * (1.f / SK);
}

// ------------------------------------------------------------------
// phase2: blocks 0-63 = top-40 per bh; blocks 64-127 = V mean per bh.
// ------------------------------------------------------------------
__global__ __launch_bounds__(512) void k_phase2(const float* __restrict__ V) {
    __shared__ unsigned long long cand[16 * U];   // topk
    __shared__ float vsm[8 * 64];                 // vmean
    int bh = blockIdx.x & 63;
    int role = blockIdx.x >> 6;
    int t = threadIdx.x;

    if (role == 1) {      // ---- vmean ----
        int b = bh >> 3, h = bh & 7;
        int d = t & 63, p = t >> 6;   // p 0..7
        float s = 0.f;
        for (int l = p; l < L; l += 8)
            s += V[(size_t)(b * L + l) * HD + h * D + d];
        vsm[p * 64 + d] = s;
        __syncthreads();
        if (t < 64) {
            float acc = 0.f;
            #pragma unroll
            for (int i = 0; i < 8; ++i) acc += vsm[i * 64 + t];
            g_vmean[bh * 64 + t] = acc * (1.f / L);
        }
        return;
    }

    // ---- topk ----
    int w = t >> 5, lane = t & 31;
    unsigned long long k[4];
    #pragma unroll
    for (int j = 0; j < 4; ++j) {
        int i = w * 128 + j * 32 + lane;
        unsigned bits = __float_as_uint(g_M[bh * L + i]);
        bits = (bits & 0x80000000u) ? ~bits : (bits | 0x80000000u);
        k[j] = ((unsigned long long)bits << 32) | (unsigned)(L - 1 - i);
    }
    for (int it = 0; it < U; ++it) {
        unsigned long long lm = k[0];
        #pragma unroll
        for (int j = 1; j < 4; ++j) if (k[j] > lm) lm = k[j];
        unsigned long long wm = lm;
        #pragma unroll
        for (int o = 16; o; o >>= 1) {
            unsigned long long x = __shfl_xor_sync(0xffffffffu, wm, o);
            if (x > wm) wm = x;
        }
        if (lane == 0) cand[w * U + it] = wm;
        #pragma unroll
        for (int j = 0; j < 4; ++j) if (k[j] == wm) k[j] = 0ull;
    }
    __syncthreads();
    for (int i = t; i < 16 * U; i += 512) {
        unsigned long long me = cand[i];
        int rank = 0;
        #pragma unroll 4
        for (int j = 0; j < 16 * U; j += 2) {
            rank += (cand[j]     > me) ? 1 : 0;
            rank += (cand[j + 1] > me) ? 1 : 0;
        }
        if (rank < U)
            g_top[bh * U + rank] = (L - 1) - (int)(me & 0xffffffffu);
    }
}

// ------------------------------------------------------------------
// phase3: blockIdx.x < KS -> fused scores+softmax+PV split;
// else -> fill slab with V-mean (hidden under attn).
// ------------------------------------------------------------------
__global__ __launch_bounds__(256, 3) void k_phase3(const float* __restrict__ Q,
                                                   const float* __restrict__ Kp,
                                                   const float* __restrict__ V,
                                                   float* __restrict__ out) {
    extern __shared__ float smem[];
    int bh = blockIdx.y;
    int b = bh >> 3, h = bh & 7;
    int t = threadIdx.x;

    if (blockIdx.x >= KS) {    // ---- fill slab ----
        int j = blockIdx.x - KS;          // 0..31
        int l0 = j * 64;
        const float4* vm4 = (const float4*)&g_vmean[bh * 64];
        float4* out4 = (float4*)out;
        #pragma unroll
        for (int kk = 0; kk < 4; ++kk) {
            int fi  = t + kk * 256;       // 0..1023
            int row = fi >> 4, c4 = fi & 15;
            out4[(size_t)(b * L + l0 + row) * (HD / 4) + h * 16 + c4] = vm4[c4];
        }
        return;
    }

    // ---- attn split ----
    float* Qsm  = smem;            // 40*64  = 2560
    float* KVsm = smem + 2560;     // 128*68 = 8704
    float* Asm  = KVsm + 8704;     // 40*132 = 5280
    int ks = blockIdx.x;
    int k0 = ks * AKT;

    for (int i = t; i < U * 16; i += 256) {
        int u = i >> 4, dq = i & 15;
        int qi = g_top[bh * U + u];
        *(float4*)&Qsm[u * 64 + dq * 4] =
            *(const float4*)&Q[(size_t)(b * L + qi) * HD + h * D + dq * 4];
    }
    for (int i = t; i < AKT * 16; i += 256) {
        int r = i >> 4, dq = i & 15;
        *(float4*)&KVsm[r * 68 + dq * 4] =
            *(const float4*)&Kp[(size_t)(b * L + k0 + r) * HD + h * D + dq * 4];
    }
    __syncthreads();

    {   // scores: thread = (kg 0..63, ug 0..3)
        int kg = t & 63, ug = t >> 6;
        float acc[10][2];
        #pragma unroll
        for (int i = 0; i < 10; ++i) { acc[i][0] = 0.f; acc[i][1] = 0.f; }
        for (int d = 0; d < 64; d += 4) {
            float4 ka = *(float4*)&KVsm[kg * 68 + d];
            float4 kb = *(float4*)&KVsm[(kg + 64) * 68 + d];
            #pragma unroll
            for (int i = 0; i < 10; ++i) {
                float4 q4 = *(float4*)&Qsm[(ug * 10 + i) * 64 + d];
                acc[i][0] = fmaf(q4.x, ka.x, acc[i][0]);
                acc[i][0] = fmaf(q4.y, ka.y, acc[i][0]);
                acc[i][0] = fmaf(q4.z, ka.z, acc[i][0]);
                acc[i][0] = fmaf(q4.w, ka.w, acc[i][0]);
                acc[i][1] = fmaf(q4.x, kb.x, acc[i][1]);
                acc[i][1] = fmaf(q4.y, kb.y, acc[i][1]);
                acc[i][1] = fmaf(q4.z, kb.z, acc[i][1]);
                acc[i][1] = fmaf(q4.w, kb.w, acc[i][1]);
            }
        }
        #pragma unroll
        for (int i = 0; i < 10; ++i) {
            Asm[(ug * 10 + i) * 132 + kg]      = acc[i][0] * SCALE;
            Asm[(ug * 10 + i) * 132 + kg + 64] = acc[i][1] * SCALE;
        }
    }
    __syncthreads();

    // V -> KVsm; per-row (m, l) stats
    for (int i = t; i < AKT * 16; i += 256) {
        int r = i >> 4, dq = i & 15;
        *(float4*)&KVsm[r * 68 + dq * 4] =
            *(const float4*)&V[(size_t)(b * L + k0 + r) * HD + h * D + dq * 4];
    }
    {
        int w = t >> 5, lane = t & 31;
        #pragma unroll
        for (int rr = 0; rr < 5; ++rr) {
            int u = w * 5 + rr;
            float vals[4], m = -3.4e38f;
            #pragma unroll
            for (int mm = 0; mm < 4; ++mm) {
                vals[mm] = Asm[u * 132 + lane + 32 * mm];
                m = fmaxf(m, vals[mm]);
            }
            #pragma unroll
            for (int o = 16; o; o >>= 1) m = fmaxf(m, __shfl_xor_sync(0xffffffffu, m, o));
            float lsum = 0.f;
            #pragma unroll
            for (int mm = 0; mm < 4; ++mm) {
                float pe = __expf(vals[mm] - m);
                Asm[u * 132 + lane + 32 * mm] = pe;
                lsum += pe;
            }
            #pragma unroll
            for (int o = 16; o; o >>= 1) lsum += __shfl_xor_sync(0xffffffffu, lsum, o);
            if (lane == 0) {
                g_ml[((bh * KS + ks) * U + u) * 2 + 0] = m;
                g_ml[((bh * KS + ks) * U + u) * 2 + 1] = lsum;
            }
        }
    }
    __syncthreads();

    {   // PV: thread = (kh 0..1, ug2 0..7, dg 0..15)
        int kh = t >> 7, ug2 = (t >> 4) & 7, dg = t & 15;
        int kb = kh * 64;
        float4 o[5];
        #pragma unroll
        for (int i = 0; i < 5; ++i) o[i] = make_float4(0.f, 0.f, 0.f, 0.f);
        for (int k = 0; k < 64; ++k) {
            float4 v = *(float4*)&KVsm[(kb + k) * 68 + dg * 4];
            #pragma unroll
            for (int i = 0; i < 5; ++i) {
                float a = Asm[(ug2 * 5 + i) * 132 + kb + k];
                o[i].x = fmaf(a, v.x, o[i].x);
                o[i].y = fmaf(a, v.y, o[i].y);
                o[i].z = fmaf(a, v.z, o[i].z);
                o[i].w = fmaf(a, v.w, o[i].w);
            }
        }
        #pragma unroll
        for (int i = 0; i < 5; ++i)
            *(float4*)&g_pv[(size_t)(((bh * KS + ks) * 2 + kh) * U + ug2 * 5 + i) * D + dg * 4] = o[i];
    }
}

// ------------------------------------------------------------------
// k_final v2: block per (bh,u); 128 threads = (sg 0..7, dq 0..15).
// Thread loads 2 splits x 2 halves (4 independent float4), scales by
// split weight, smem tree-reduce over sg. High-MLP, DRAM-floor bound.
// ------------------------------------------------------------------
__global__ __launch_bounds__(128) void k_final2(float* __restrict__ out) {
    __shared__ float4 red[8][16];
    int bu = blockIdx.x;            // 0 .. BH*U-1
    int u  = bu % U;
    int bh = bu / U;
    int t = threadIdx.x;
    int sg = t >> 4, dq = t & 15;   // sg 0..7, dq 0..15

    // stats over all 16 splits (uniform per block; L1-broadcast)
    float M = -3.4e38f;
    float mv[KS];
    #pragma unroll
    for (int s = 0; s < KS; ++s) {
        mv[s] = g_ml[((bh * KS + s) * U + u) * 2 + 0];
        M = fmaxf(M, mv[s]);
    }
    float lsum = 0.f;
    #pragma unroll
    for (int s = 0; s < KS; ++s)
        lsum += __expf(mv[s] - M) * g_ml[((bh * KS + s) * U + u) * 2 + 1];

    // this thread's 2 splits
    float4 acc = make_float4(0.f, 0.f, 0.f, 0.f);
    #pragma unroll
    for (int j = 0; j < 2; ++j) {
        int s = sg * 2 + j;
        float wgt = __expf(mv[s] - M);
        float4 p0 = *(const float4*)&g_pv[(size_t)(((bh * KS + s) * 2 + 0) * U + u) * D + dq * 4];
        float4 p1 = *(const float4*)&g_pv[(size_t)(((bh * KS + s) * 2 + 1) * U + u) * D + dq * 4];
        acc.x = fmaf(wgt, p0.x + p1.x, acc.x);
        acc.y = fmaf(wgt, p0.y + p1.y, acc.y);
        acc.z = fmaf(wgt, p0.z + p1.z, acc.z);
        acc.w = fmaf(wgt, p0.w + p1.w, acc.w);
    }
    red[sg][dq] = acc;
    __syncthreads();
    if (sg == 0) {
        float4 s4 = red[0][dq];
        #pragma unroll
        for (int i = 1; i < 8; ++i) {
            float4 p = red[i][dq];
            s4.x += p.x; s4.y += p.y; s4.z += p.z; s4.w += p.w;
        }
        float inv = 1.f / lsum;
        int q = g_top[bh * U + u];
        int b = bh >> 3, h = bh & 7;
        *(float4*)&out[(size_t)(b * L + q) * HD + h * D + dq * 4] =
            make_float4(s4.x * inv, s4.y * inv, s4.z * inv, s4.w * inv);
    }
}

// ------------------------------------------------------------------
extern "C" void kernel_launch(void* const* d_in, const int* in_sizes, int n_in,
                              void* d_out, int out_size) {
    const float* Q = (const float*)d_in[0];
    const float* K = (const float*)d_in[1];
    const float* V = (const float*)d_in[2];
    const int*  IS = (const int*)d_in[3];
    float* out = (float*)d_out;

    const int smem_attn = (2560 + 8704 + 5280) * 4;   // 66176
    cudaFuncSetAttribute(k_phase3, cudaFuncAttributeMaxDynamicSharedMemorySize, smem_attn);

    k_probe_M<<<(BH * L / 2) / 8, 256>>>(Q, K, IS);                 // 8192 blocks
    k_phase2 <<<128, 512>>>(V);                                     // topk || vmean
    k_phase3 <<<dim3(KS + FILLB, BH), 256, smem_attn>>>(Q, K, V, out); // attn || fill
    k_final2 <<<BH * U, 128>>>(out);
}